// round 9
// baseline (speedup 1.0000x reference)
#include <cuda_runtime.h>
#include <math.h>
#include <stdint.h>

#define B_ 8
#define N_ 4096
#define C_ 256
#define K_ 32
#define M_ (B_*N_)

// Scratch
__device__ __align__(16) float g_feat[M_*C_];
__device__ __align__(16) float g_pos[M_*C_];

// ---- packed fp32x2 helpers (PTX fma.rn.f32x2, sm_100+; FFMA2 in SASS) ----
__device__ __forceinline__ unsigned long long pack2(float x) {
    unsigned long long r;
    asm("mov.b64 %0, {%1, %1};" : "=l"(r) : "f"(x));
    return r;
}
__device__ __forceinline__ void fma2(unsigned long long& d,
                                     unsigned long long a, unsigned long long b) {
    asm("fma.rn.f32x2 %0, %1, %2, %0;" : "+l"(d) : "l"(a), "l"(b));
}
__device__ __forceinline__ float2 unpack2(unsigned long long v) {
    float2 f;
    asm("mov.b64 {%0, %1}, %2;" : "=f"(f.x), "=f"(f.y) : "l"(v));
    return f;
}

// ---------------------------------------------------------------------------
// Kernel 1: feat_pos = x @ W^T + bias ; split into g_feat / g_pos
// grid (8, 512), block 256 (ty=tid>>3 -> 2 rows, tx=tid&7 -> 8 cols), f32x2
// ---------------------------------------------------------------------------
__global__ __launch_bounds__(256, 2) void gemm_feat_pos(
    const float* __restrict__ x, const float* __restrict__ W,
    const float* __restrict__ bias)
{
    __shared__ float as[16][64];   // [c][row]
    __shared__ float bs[16][64];   // [c][d]
    const int tid = threadIdx.x;
    const int row0 = blockIdx.y * 64;
    const int d0   = blockIdx.x * 64;
    const int tx = tid & 7, ty = tid >> 3;
    const int lr = tid >> 2, lc = tid & 3;
    unsigned long long acc[2][4] = {};
    for (int kt = 0; kt < C_; kt += 16) {
        float4 va = *(const float4*)&x[(row0 + lr) * C_ + kt + lc * 4];
        float4 vb = *(const float4*)&W[(d0 + lr) * C_ + kt + lc * 4];
        as[lc*4+0][lr]=va.x; as[lc*4+1][lr]=va.y; as[lc*4+2][lr]=va.z; as[lc*4+3][lr]=va.w;
        bs[lc*4+0][lr]=vb.x; bs[lc*4+1][lr]=vb.y; bs[lc*4+2][lr]=vb.z; bs[lc*4+3][lr]=vb.w;
        __syncthreads();
        #pragma unroll
        for (int kk = 0; kk < 16; kk++) {
            float2 av = *(const float2*)&as[kk][ty*2];
            ulonglong2 b0 = *(const ulonglong2*)&bs[kk][tx*8];
            ulonglong2 b1 = *(const ulonglong2*)&bs[kk][tx*8 + 4];
            unsigned long long p0 = pack2(av.x), p1 = pack2(av.y);
            fma2(acc[0][0], p0, b0.x); fma2(acc[0][1], p0, b0.y);
            fma2(acc[0][2], p0, b1.x); fma2(acc[0][3], p0, b1.y);
            fma2(acc[1][0], p1, b0.x); fma2(acc[1][1], p1, b0.y);
            fma2(acc[1][2], p1, b1.x); fma2(acc[1][3], p1, b1.y);
        }
        __syncthreads();
    }
    #pragma unroll
    for (int i = 0; i < 2; i++) {
        int row = row0 + ty*2 + i;
        #pragma unroll
        for (int j = 0; j < 4; j++) {
            int d = d0 + tx*8 + j*2;
            float2 f = unpack2(acc[i][j]);
            float v0 = f.x + bias[d];
            float v1 = f.y + bias[d+1];
            if (d < C_) {
                g_feat[row*C_ + d]     = v0;
                g_feat[row*C_ + d + 1] = v1;
            } else {
                g_pos[row*C_ + d - C_]     = v0;
                g_pos[row*C_ + d - C_ + 1] = v1;
            }
        }
    }
}

// ---------------------------------------------------------------------------
// Kernel 2: normalize pos rows in place. grid = M, block = 64
// ---------------------------------------------------------------------------
__global__ __launch_bounds__(64) void norm_pos()
{
    const int row = blockIdx.x;
    float* p = g_pos + (size_t)row * C_;
    const int t = threadIdx.x;
    float4 v = *(float4*)&p[t*4];
    float ss = v.x*v.x + v.y*v.y + v.z*v.z + v.w*v.w;
    #pragma unroll
    for (int o = 16; o; o >>= 1) ss += __shfl_xor_sync(0xFFFFFFFFu, ss, o);
    __shared__ float s2[2];
    if ((t & 31) == 0) s2[t >> 5] = ss;
    __syncthreads();
    float inv = 1.0f / fmaxf(sqrtf(s2[0] + s2[1]), 1e-12f);
    v.x*=inv; v.y*=inv; v.z*=inv; v.w*=inv;
    *(float4*)&p[t*4] = v;
}

// ---------------------------------------------------------------------------
// Kernel 3: fused sim GEMM (f32x2) + streaming top-32 + softmax + gather
// grid = (N/64, B), block = 256, smem 102656B -> 2 blocks/SM
// smem float layout (identical to R5):
//   qs:  [256][64]  q-tile c-major      off 0      len 16384
//   ks:  [16][64]   key chunk           off 16384  len 1024
//   st:  [64][65]   S tile (padded)     off 17408  len 4160
//   tv:  [32][64]   top values          off 21568  len 2048
//   ti:  [32][64]   top indices         off 23616  len 2048
// ---------------------------------------------------------------------------
#define SMEM_FLOATS 25664

__global__ __launch_bounds__(256, 2) void topk_attn(float* __restrict__ out)
{
    extern __shared__ float sm[];
    float* qs = sm;
    float* ks = sm + 16384;
    float* st = sm + 17408;
    float* tv = sm + 21568;
    int*   ti = (int*)(sm + 23616);

    const int tid = threadIdx.x;
    const int batch = blockIdx.y;
    const int q0 = blockIdx.x * 64;
    const float* posb = g_pos + (size_t)batch * N_ * C_;

    // load 64x256 q tile, transposed to c-major
    #pragma unroll
    for (int it = 0; it < 16; it++) {
        int f4 = it * 256 + tid;
        int r = f4 >> 6, c4 = f4 & 63;
        float4 v = *(const float4*)&posb[(q0 + r) * C_ + c4 * 4];
        qs[(c4*4+0)*64+r]=v.x; qs[(c4*4+1)*64+r]=v.y;
        qs[(c4*4+2)*64+r]=v.z; qs[(c4*4+3)*64+r]=v.w;
    }

    // per-row top-k state (thread tid<64 owns row tid)
    int cnt = 0, thrp = 0;
    float thrv = 3.0e38f;

    const int tx = tid & 7, ty = tid >> 3;
    const int lr = tid >> 2, lc = tid & 3;
    __syncthreads();

    for (int kt0 = 0; kt0 < N_; kt0 += 64) {
        unsigned long long acc[2][4] = {};
        for (int c0 = 0; c0 < C_; c0 += 16) {
            float4 v = *(const float4*)&posb[(kt0 + lr) * C_ + c0 + lc*4];
            ks[(lc*4+0)*64+lr]=v.x; ks[(lc*4+1)*64+lr]=v.y;
            ks[(lc*4+2)*64+lr]=v.z; ks[(lc*4+3)*64+lr]=v.w;
            __syncthreads();
            #pragma unroll
            for (int kk = 0; kk < 16; kk++) {
                float2 av = *(const float2*)&qs[(c0+kk)*64 + ty*2];
                ulonglong2 b0 = *(const ulonglong2*)&ks[kk*64 + tx*8];
                ulonglong2 b1 = *(const ulonglong2*)&ks[kk*64 + tx*8 + 4];
                unsigned long long p0 = pack2(av.x), p1 = pack2(av.y);
                fma2(acc[0][0], p0, b0.x); fma2(acc[0][1], p0, b0.y);
                fma2(acc[0][2], p0, b1.x); fma2(acc[0][3], p0, b1.y);
                fma2(acc[1][0], p1, b0.x); fma2(acc[1][1], p1, b0.y);
                fma2(acc[1][2], p1, b1.x); fma2(acc[1][3], p1, b1.y);
            }
            __syncthreads();
        }
        // dump S tile (scalar stores; stride 65)
        #pragma unroll
        for (int i = 0; i < 2; i++) {
            float* srow = &st[(ty*2+i)*65 + tx*8];
            #pragma unroll
            for (int j = 0; j < 4; j++) {
                float2 f = unpack2(acc[i][j]);
                srow[j*2]     = f.x;
                srow[j*2 + 1] = f.y;
            }
        }
        __syncthreads();
        // streaming top-32 per row
        if (tid < 64) {
            const int r = tid;
            #pragma unroll 8
            for (int j = 0; j < 64; j++) {
                float v = st[r*65 + j];
                if (cnt < K_) {
                    tv[cnt*64 + r] = v; ti[cnt*64 + r] = kt0 + j;
                    if (v < thrv) { thrv = v; thrp = cnt; }
                    cnt++;
                } else if (v > thrv) {
                    tv[thrp*64 + r] = v; ti[thrp*64 + r] = kt0 + j;
                    thrv = tv[r]; thrp = 0;
                    #pragma unroll
                    for (int i = 1; i < K_; i++) {
                        float t2 = tv[i*64 + r];
                        if (t2 < thrv) { thrv = t2; thrp = i; }
                    }
                }
            }
        }
        __syncthreads();
    }

    // softmax per row (order-invariant)
    if (tid < 64) {
        const int r = tid;
        float m = -3.0e38f;
        #pragma unroll
        for (int i = 0; i < K_; i++) m = fmaxf(m, tv[i*64 + r]);
        float s = 0.f;
        #pragma unroll
        for (int i = 0; i < K_; i++) { float e = expf(tv[i*64 + r] - m); tv[i*64 + r] = e; s += e; }
        float inv = 1.0f / s;
        #pragma unroll
        for (int i = 0; i < K_; i++) tv[i*64 + r] *= inv;
    }
    __syncthreads();

    // gather: 8 warps, one row each, 8 floats/lane
    const int warp = tid >> 5, lane = tid & 31;
    const float* fb = g_feat + (size_t)batch * N_ * C_;
    for (int rr = warp; rr < 64; rr += 8) {
        float a0[4] = {0.f,0.f,0.f,0.f}, a1[4] = {0.f,0.f,0.f,0.f};
        #pragma unroll 4
        for (int i = 0; i < K_; i++) {
            float w = tv[i*64 + rr];
            const float* f = fb + (size_t)ti[i*64 + rr]*C_ + lane*8;
            float4 u  = *(const float4*)f;
            float4 u2 = *(const float4*)(f + 4);
            a0[0]+=w*u.x;  a0[1]+=w*u.y;  a0[2]+=w*u.z;  a0[3]+=w*u.w;
            a1[0]+=w*u2.x; a1[1]+=w*u2.y; a1[2]+=w*u2.z; a1[3]+=w*u2.w;
        }
        float* o = out + ((size_t)batch*N_ + q0 + rr)*C_ + lane*8;
        *(float4*)o       = make_float4(a0[0],a0[1],a0[2],a0[3]);
        *(float4*)(o + 4) = make_float4(a1[0],a1[1],a1[2],a1[3]);
    }
}

// ---------------------------------------------------------------------------
extern "C" void kernel_launch(void* const* d_in, const int* in_sizes, int n_in,
                              void* d_out, int out_size)
{
    const float* x    = (const float*)d_in[0];
    const float* W    = (const float*)d_in[1];
    const float* bias = (const float*)d_in[2];
    float* out = (float*)d_out;

    gemm_feat_pos<<<dim3(8, M_/64), 256>>>(x, W, bias);
    norm_pos<<<M_, 64>>>();

    const int smem_bytes = SMEM_FLOATS * (int)sizeof(float);
    cudaFuncSetAttribute(topk_attn, cudaFuncAttributeMaxDynamicSharedMemorySize,
                         smem_bytes);
    topk_attn<<<dim3(N_/64, B_), 256, smem_bytes>>>(out);
}

// round 12
// speedup vs baseline: 2.2861x; 2.2861x over previous
#include <cuda_runtime.h>
#include <math.h>
#include <stdint.h>

#define B_ 8
#define N_ 4096
#define C_ 256
#define K_ 32
#define M_ (B_*N_)

// Scratch
__device__ __align__(16) float g_feat[M_*C_];
__device__ __align__(16) float g_pos[M_*C_];

// ---------------------------------------------------------------------------
// Kernel 1: feat_pos = x @ W^T + bias ; split into g_feat / g_pos  (R5 proven)
// ---------------------------------------------------------------------------
__global__ __launch_bounds__(256) void gemm_feat_pos(
    const float* __restrict__ x, const float* __restrict__ W,
    const float* __restrict__ bias)
{
    __shared__ float as[16][64];
    __shared__ float bs[16][64];
    const int tid = threadIdx.x;
    const int row0 = blockIdx.y * 64;
    const int d0   = blockIdx.x * 64;
    const int tx = tid & 15, ty = tid >> 4;
    const int lr = tid >> 2, lc = tid & 3;
    float acc[4][4] = {};
    for (int kt = 0; kt < C_; kt += 16) {
        float4 va = *(const float4*)&x[(row0 + lr) * C_ + kt + lc * 4];
        float4 vb = *(const float4*)&W[(d0 + lr) * C_ + kt + lc * 4];
        as[lc*4+0][lr]=va.x; as[lc*4+1][lr]=va.y; as[lc*4+2][lr]=va.z; as[lc*4+3][lr]=va.w;
        bs[lc*4+0][lr]=vb.x; bs[lc*4+1][lr]=vb.y; bs[lc*4+2][lr]=vb.z; bs[lc*4+3][lr]=vb.w;
        __syncthreads();
        #pragma unroll
        for (int kk = 0; kk < 16; kk++) {
            float4 a = *(const float4*)&as[kk][ty*4];
            float4 b = *(const float4*)&bs[kk][tx*4];
            float ar[4]={a.x,a.y,a.z,a.w}, br[4]={b.x,b.y,b.z,b.w};
            #pragma unroll
            for (int i=0;i<4;i++)
                #pragma unroll
                for (int j=0;j<4;j++) acc[i][j] += ar[i]*br[j];
        }
        __syncthreads();
    }
    #pragma unroll
    for (int i=0;i<4;i++) {
        int row = row0 + ty*4 + i;
        #pragma unroll
        for (int j=0;j<4;j++) {
            int d = d0 + tx*4 + j;
            float v = acc[i][j] + bias[d];
            if (d < C_) g_feat[row*C_ + d] = v;
            else        g_pos[row*C_ + d - C_] = v;
        }
    }
}

// ---------------------------------------------------------------------------
// Kernel 2: normalize pos rows in place. grid = M, block = 64  (R5 proven)
// ---------------------------------------------------------------------------
__global__ __launch_bounds__(64) void norm_pos()
{
    const int row = blockIdx.x;
    float* p = g_pos + (size_t)row * C_;
    const int t = threadIdx.x;
    float4 v = *(float4*)&p[t*4];
    float ss = v.x*v.x + v.y*v.y + v.z*v.z + v.w*v.w;
    #pragma unroll
    for (int o = 16; o; o >>= 1) ss += __shfl_xor_sync(0xFFFFFFFFu, ss, o);
    __shared__ float s2[2];
    if ((t & 31) == 0) s2[t >> 5] = ss;
    __syncthreads();
    float inv = 1.0f / fmaxf(sqrtf(s2[0] + s2[1]), 1e-12f);
    v.x*=inv; v.y*=inv; v.z*=inv; v.w*=inv;
    *(float4*)&p[t*4] = v;
}

// ---------------------------------------------------------------------------
// Kernel 3: fused sim GEMM + streaming top-32 + softmax + gather
// 128 q-rows x 64-key tiles, 256 threads, 8x4 microtile (FMA-bound),
// 8-dim chunks, register-prefetch + double-buffered smem, 1 sync/chunk.
// smem float layout:
//   AB  [2][8][128]  q chunk (c-major)   off 0      len 2048
//   BB  [2][8][64]   key chunk           off 2048   len 1024
//   S   [128][65]    S tile (scalar st)  off 3072   len 8320
//   TV  [32][128]    top values          off 11392  len 4096
//   TI  u16[32][128] top indices         off 15488  len 2048 (floats)
// total 17536 floats = 70144 B  -> 2 blocks/SM, grid 256 = 1 wave
// ---------------------------------------------------------------------------
#define AB0   0
#define BB0   2048
#define SOFF  3072
#define TVOFF 11392
#define TIOFF 15488
#define SMEM_FLOATS 17536

__global__ __launch_bounds__(256, 2) void topk_attn(float* __restrict__ out)
{
    extern __shared__ float sm[];
    float* S  = sm + SOFF;
    float* tv = sm + TVOFF;
    uint16_t* ti = (uint16_t*)(sm + TIOFF);

    const int tid = threadIdx.x;
    const int w = tid >> 5, lane = tid & 31;
    const int batch = blockIdx.y;
    const int q0 = blockIdx.x * 128;
    const float* posb = g_pos + ((size_t)batch * N_ << 8);

    const int tx = tid & 15, ty = tid >> 4;      // 16x16 thread grid
    const int lrow = tid >> 1, lc4 = tid & 1;    // A loader map (128 rows x 2)
    const int brow = tid >> 1;                    // B loader map (tid<128: 64 keys x 2)

    // per-row top-k state (thread tid<128 owns q-row tid)
    int cnt = 0, thrp = 0;
    float thrv = 3.0e38f;

    for (int tile = 0; tile < 64; tile++) {
        const int kt0 = tile * 64;
        float acc[8][4] = {};

        // prefetch chunk 0
        float4 pa = *(const float4*)&posb[((q0 + lrow) << 8) + lc4*4];
        float4 pb;
        if (tid < 128)
            pb = *(const float4*)&posb[((kt0 + brow) << 8) + lc4*4];

        for (int ch = 0; ch < 32; ch++) {
            const int buf = ch & 1;
            // store prefetched regs -> smem
            {
                float* A = sm + AB0 + buf*1024;
                A[(lc4*4+0)*128 + lrow] = pa.x;
                A[(lc4*4+1)*128 + lrow] = pa.y;
                A[(lc4*4+2)*128 + lrow] = pa.z;
                A[(lc4*4+3)*128 + lrow] = pa.w;
                if (tid < 128) {
                    float* Bp = sm + BB0 + buf*512;
                    Bp[(lc4*4+0)*64 + brow] = pb.x;
                    Bp[(lc4*4+1)*64 + brow] = pb.y;
                    Bp[(lc4*4+2)*64 + brow] = pb.z;
                    Bp[(lc4*4+3)*64 + brow] = pb.w;
                }
            }
            // prefetch next chunk
            if (ch + 1 < 32) {
                const int c0 = (ch + 1) * 8;
                pa = *(const float4*)&posb[((q0 + lrow) << 8) + c0 + lc4*4];
                if (tid < 128)
                    pb = *(const float4*)&posb[((kt0 + brow) << 8) + c0 + lc4*4];
            }
            __syncthreads();
            // compute 8 kk on this buffer (no trailing sync: double-buffered)
            const float* A  = sm + AB0 + buf*1024;
            const float* Bp = sm + BB0 + buf*512;
            #pragma unroll
            for (int kk = 0; kk < 8; kk++) {
                float4 a0 = *(const float4*)&A[kk*128 + ty*8];
                float4 a1 = *(const float4*)&A[kk*128 + ty*8 + 4];
                float4 b  = *(const float4*)&Bp[kk*64 + tx*4];
                float ar[8] = {a0.x,a0.y,a0.z,a0.w,a1.x,a1.y,a1.z,a1.w};
                float br[4] = {b.x,b.y,b.z,b.w};
                #pragma unroll
                for (int i = 0; i < 8; i++)
                    #pragma unroll
                    for (int j = 0; j < 4; j++)
                        acc[i][j] += ar[i]*br[j];
            }
        }
        __syncthreads();
        // dump S tile (scalar stores; stride 65)
        #pragma unroll
        for (int i = 0; i < 8; i++) {
            float* srow = &S[(ty*8+i)*65 + tx*4];
            #pragma unroll
            for (int j = 0; j < 4; j++) srow[j] = acc[i][j];
        }
        __syncthreads();
        // streaming top-32 per row
        if (tid < 128) {
            const int r = tid;
            #pragma unroll 8
            for (int j = 0; j < 64; j++) {
                float v = S[r*65 + j];
                if (cnt < K_) {
                    tv[cnt*128 + r] = v; ti[cnt*128 + r] = (uint16_t)(kt0 + j);
                    if (v < thrv) { thrv = v; thrp = cnt; }
                    cnt++;
                } else if (v > thrv) {
                    tv[thrp*128 + r] = v; ti[thrp*128 + r] = (uint16_t)(kt0 + j);
                    thrv = tv[r]; thrp = 0;
                    #pragma unroll
                    for (int i = 1; i < K_; i++) {
                        float t2 = tv[i*128 + r];
                        if (t2 < thrv) { thrv = t2; thrp = i; }
                    }
                }
            }
        }
        __syncthreads();
    }

    // softmax per row (order-invariant)
    if (tid < 128) {
        const int r = tid;
        float m = -3.0e38f;
        #pragma unroll
        for (int i = 0; i < K_; i++) m = fmaxf(m, tv[i*128 + r]);
        float s = 0.f;
        #pragma unroll
        for (int i = 0; i < K_; i++) { float e = expf(tv[i*128 + r] - m); tv[i*128 + r] = e; s += e; }
        float inv = 1.0f / s;
        #pragma unroll
        for (int i = 0; i < K_; i++) tv[i*128 + r] *= inv;
    }
    __syncthreads();

    // gather: 8 warps, 16 rows each, 8 floats/lane
    const float* fb = g_feat + ((size_t)batch * N_ << 8);
    for (int rr = w; rr < 128; rr += 8) {
        float a0[4] = {0.f,0.f,0.f,0.f}, a1[4] = {0.f,0.f,0.f,0.f};
        #pragma unroll 4
        for (int i = 0; i < K_; i++) {
            float wt = tv[i*128 + rr];
            const float* f = fb + ((size_t)ti[i*128 + rr] << 8) + lane*8;
            float4 u  = *(const float4*)f;
            float4 u2 = *(const float4*)(f + 4);
            a0[0]+=wt*u.x;  a0[1]+=wt*u.y;  a0[2]+=wt*u.z;  a0[3]+=wt*u.w;
            a1[0]+=wt*u2.x; a1[1]+=wt*u2.y; a1[2]+=wt*u2.z; a1[3]+=wt*u2.w;
        }
        float* o = out + (((size_t)batch * N_ + q0 + rr) << 8) + lane*8;
        *(float4*)o       = make_float4(a0[0],a0[1],a0[2],a0[3]);
        *(float4*)(o + 4) = make_float4(a1[0],a1[1],a1[2],a1[3]);
    }
}

// ---------------------------------------------------------------------------
extern "C" void kernel_launch(void* const* d_in, const int* in_sizes, int n_in,
                              void* d_out, int out_size)
{
    const float* x    = (const float*)d_in[0];
    const float* W    = (const float*)d_in[1];
    const float* bias = (const float*)d_in[2];
    float* out = (float*)d_out;

    gemm_feat_pos<<<dim3(512/64, M_/64), 256>>>(x, W, bias);
    norm_pos<<<M_, 64>>>();

    const int smem_bytes = SMEM_FLOATS * (int)sizeof(float);
    cudaFuncSetAttribute(topk_attn, cudaFuncAttributeMaxDynamicSharedMemorySize,
                         smem_bytes);
    topk_attn<<<dim3(N_/128, B_), 256, smem_bytes>>>(out);
}

// round 14
// speedup vs baseline: 2.4033x; 1.0513x over previous
#include <cuda_runtime.h>
#include <math.h>
#include <stdint.h>

#define B_ 8
#define N_ 4096
#define C_ 256
#define K_ 32
#define M_ (B_*N_)

// Scratch
__device__ __align__(16) float g_feat[M_*C_];
__device__ __align__(16) float g_pos[M_*C_];

// ---- packed fp32x2 helpers (FFMA2 via PTX fma.rn.f32x2) ----
__device__ __forceinline__ unsigned long long pack2(float x) {
    unsigned long long r;
    asm("mov.b64 %0, {%1, %1};" : "=l"(r) : "f"(x));
    return r;
}
__device__ __forceinline__ void fma2(unsigned long long& d,
                                     unsigned long long a, unsigned long long b) {
    asm("fma.rn.f32x2 %0, %1, %2, %0;" : "+l"(d) : "l"(a), "l"(b));
}
__device__ __forceinline__ float2 unpack2(unsigned long long v) {
    float2 f;
    asm("mov.b64 {%0, %1}, %2;" : "=f"(f.x), "=f"(f.y) : "l"(v));
    return f;
}

// ---------------------------------------------------------------------------
// Kernel 1: feat_pos = x @ W^T + bias ; split into g_feat / g_pos  (R5 proven)
// ---------------------------------------------------------------------------
__global__ __launch_bounds__(256) void gemm_feat_pos(
    const float* __restrict__ x, const float* __restrict__ W,
    const float* __restrict__ bias)
{
    __shared__ float as[16][64];
    __shared__ float bs[16][64];
    const int tid = threadIdx.x;
    const int row0 = blockIdx.y * 64;
    const int d0   = blockIdx.x * 64;
    const int tx = tid & 15, ty = tid >> 4;
    const int lr = tid >> 2, lc = tid & 3;
    float acc[4][4] = {};
    for (int kt = 0; kt < C_; kt += 16) {
        float4 va = *(const float4*)&x[(row0 + lr) * C_ + kt + lc * 4];
        float4 vb = *(const float4*)&W[(d0 + lr) * C_ + kt + lc * 4];
        as[lc*4+0][lr]=va.x; as[lc*4+1][lr]=va.y; as[lc*4+2][lr]=va.z; as[lc*4+3][lr]=va.w;
        bs[lc*4+0][lr]=vb.x; bs[lc*4+1][lr]=vb.y; bs[lc*4+2][lr]=vb.z; bs[lc*4+3][lr]=vb.w;
        __syncthreads();
        #pragma unroll
        for (int kk = 0; kk < 16; kk++) {
            float4 a = *(const float4*)&as[kk][ty*4];
            float4 b = *(const float4*)&bs[kk][tx*4];
            float ar[4]={a.x,a.y,a.z,a.w}, br[4]={b.x,b.y,b.z,b.w};
            #pragma unroll
            for (int i=0;i<4;i++)
                #pragma unroll
                for (int j=0;j<4;j++) acc[i][j] += ar[i]*br[j];
        }
        __syncthreads();
    }
    #pragma unroll
    for (int i=0;i<4;i++) {
        int row = row0 + ty*4 + i;
        #pragma unroll
        for (int j=0;j<4;j++) {
            int d = d0 + tx*4 + j;
            float v = acc[i][j] + bias[d];
            if (d < C_) g_feat[row*C_ + d] = v;
            else        g_pos[row*C_ + d - C_] = v;
        }
    }
}

// ---------------------------------------------------------------------------
// Kernel 2: normalize pos rows in place. grid = M, block = 64  (R5 proven)
// ---------------------------------------------------------------------------
__global__ __launch_bounds__(64) void norm_pos()
{
    const int row = blockIdx.x;
    float* p = g_pos + (size_t)row * C_;
    const int t = threadIdx.x;
    float4 v = *(float4*)&p[t*4];
    float ss = v.x*v.x + v.y*v.y + v.z*v.z + v.w*v.w;
    #pragma unroll
    for (int o = 16; o; o >>= 1) ss += __shfl_xor_sync(0xFFFFFFFFu, ss, o);
    __shared__ float s2[2];
    if ((t & 31) == 0) s2[t >> 5] = ss;
    __syncthreads();
    float inv = 1.0f / fmaxf(sqrtf(s2[0] + s2[1]), 1e-12f);
    v.x*=inv; v.y*=inv; v.z*=inv; v.w*=inv;
    *(float4*)&p[t*4] = v;
}

// ---------------------------------------------------------------------------
// Kernel 3: fused sim GEMM (FFMA2) + streaming top-32 + softmax + gather
// R12 structure; inner product converted to fma.rn.f32x2:
//   A c-major float4 = 4 adjacent q-rows = 2 natural f32x2 pairs (no repack),
//   B broadcast-packed (4 mov.b64/kk, alu pipe overlaps fma pipe).
//   16 FFMA2/kk (32 fma cyc) vs 32 FFMA/kk (64 cyc) -> 2x mainloop.
// smem float layout (identical to R12):
//   AB  [2][8][128]  q chunk (c-major)   off 0      len 2048
//   BB  [2][8][64]   key chunk           off 2048   len 1024
//   S   [128][65]    S tile (scalar st)  off 3072   len 8320
//   TV  [32][128]    top values          off 11392  len 4096
//   TI  u16[32][128] top indices         off 15488  len 2048 (floats)
// total 17536 floats = 70144 B -> 2 blocks/SM, grid 256 = 1 wave
// ---------------------------------------------------------------------------
#define AB0   0
#define BB0   2048
#define SOFF  3072
#define TVOFF 11392
#define TIOFF 15488
#define SMEM_FLOATS 17536

__global__ __launch_bounds__(256, 2) void topk_attn(float* __restrict__ out)
{
    extern __shared__ float sm[];
    float* S  = sm + SOFF;
    float* tv = sm + TVOFF;
    uint16_t* ti = (uint16_t*)(sm + TIOFF);

    const int tid = threadIdx.x;
    const int w = tid >> 5, lane = tid & 31;
    const int batch = blockIdx.y;
    const int q0 = blockIdx.x * 128;
    const float* posb = g_pos + ((size_t)batch * N_ << 8);

    const int tx = tid & 15, ty = tid >> 4;      // 16x16 thread grid
    const int lrow = tid >> 1, lc4 = tid & 1;    // A loader map (128 rows x 2)
    const int brow = tid >> 1;                    // B loader map (tid<128)

    // per-row top-k state (thread tid<128 owns q-row tid)
    int cnt = 0, thrp = 0;
    float thrv = 3.0e38f;

    for (int tile = 0; tile < 64; tile++) {
        const int kt0 = tile * 64;
        // acc2[i2][j]: rows (ty*8+2*i2, +1) x col (tx*4+j), packed f32x2
        unsigned long long acc2[4][4] = {};

        // prefetch chunk 0
        float4 pa = *(const float4*)&posb[((q0 + lrow) << 8) + lc4*4];
        float4 pb;
        if (tid < 128)
            pb = *(const float4*)&posb[((kt0 + brow) << 8) + lc4*4];

        for (int ch = 0; ch < 32; ch++) {
            const int buf = ch & 1;
            // store prefetched regs -> smem
            {
                float* A = sm + AB0 + buf*1024;
                A[(lc4*4+0)*128 + lrow] = pa.x;
                A[(lc4*4+1)*128 + lrow] = pa.y;
                A[(lc4*4+2)*128 + lrow] = pa.z;
                A[(lc4*4+3)*128 + lrow] = pa.w;
                if (tid < 128) {
                    float* Bp = sm + BB0 + buf*512;
                    Bp[(lc4*4+0)*64 + brow] = pb.x;
                    Bp[(lc4*4+1)*64 + brow] = pb.y;
                    Bp[(lc4*4+2)*64 + brow] = pb.z;
                    Bp[(lc4*4+3)*64 + brow] = pb.w;
                }
            }
            // prefetch next chunk
            if (ch + 1 < 32) {
                const int c0 = (ch + 1) * 8;
                pa = *(const float4*)&posb[((q0 + lrow) << 8) + c0 + lc4*4];
                if (tid < 128)
                    pb = *(const float4*)&posb[((kt0 + brow) << 8) + c0 + lc4*4];
            }
            __syncthreads();
            // compute 8 kk on this buffer (double-buffered, no trailing sync)
            const float* A  = sm + AB0 + buf*1024;
            const float* Bp = sm + BB0 + buf*512;
            #pragma unroll
            for (int kk = 0; kk < 8; kk++) {
                ulonglong2 a01 = *(const ulonglong2*)&A[kk*128 + ty*8];     // rows 0..3
                ulonglong2 a23 = *(const ulonglong2*)&A[kk*128 + ty*8 + 4]; // rows 4..7
                float4 b = *(const float4*)&Bp[kk*64 + tx*4];
                unsigned long long ar[4] = {a01.x, a01.y, a23.x, a23.y};
                unsigned long long bp[4] = {pack2(b.x), pack2(b.y), pack2(b.z), pack2(b.w)};
                #pragma unroll
                for (int i2 = 0; i2 < 4; i2++)
                    #pragma unroll
                    for (int j = 0; j < 4; j++)
                        fma2(acc2[i2][j], ar[i2], bp[j]);
            }
        }
        __syncthreads();
        // dump S tile (scalar stores; stride 65). lane i2 -> rows 2*i2, 2*i2+1
        #pragma unroll
        for (int i2 = 0; i2 < 4; i2++) {
            float* r0 = &S[(ty*8 + i2*2)*65 + tx*4];
            float* r1 = &S[(ty*8 + i2*2 + 1)*65 + tx*4];
            #pragma unroll
            for (int j = 0; j < 4; j++) {
                float2 f = unpack2(acc2[i2][j]);
                r0[j] = f.x;
                r1[j] = f.y;
            }
        }
        __syncthreads();
        // streaming top-32 per row
        if (tid < 128) {
            const int r = tid;
            #pragma unroll 8
            for (int j = 0; j < 64; j++) {
                float v = S[r*65 + j];
                if (cnt < K_) {
                    tv[cnt*128 + r] = v; ti[cnt*128 + r] = (uint16_t)(kt0 + j);
                    if (v < thrv) { thrv = v; thrp = cnt; }
                    cnt++;
                } else if (v > thrv) {
                    tv[thrp*128 + r] = v; ti[thrp*128 + r] = (uint16_t)(kt0 + j);
                    thrv = tv[r]; thrp = 0;
                    #pragma unroll
                    for (int i = 1; i < K_; i++) {
                        float t2 = tv[i*128 + r];
                        if (t2 < thrv) { thrv = t2; thrp = i; }
                    }
                }
            }
        }
        __syncthreads();
    }

    // softmax per row (order-invariant)
    if (tid < 128) {
        const int r = tid;
        float m = -3.0e38f;
        #pragma unroll
        for (int i = 0; i < K_; i++) m = fmaxf(m, tv[i*128 + r]);
        float s = 0.f;
        #pragma unroll
        for (int i = 0; i < K_; i++) { float e = expf(tv[i*128 + r] - m); tv[i*128 + r] = e; s += e; }
        float inv = 1.0f / s;
        #pragma unroll
        for (int i = 0; i < K_; i++) tv[i*128 + r] *= inv;
    }
    __syncthreads();

    // gather: 8 warps, 16 rows each, 8 floats/lane
    const float* fb = g_feat + ((size_t)batch * N_ << 8);
    for (int rr = w; rr < 128; rr += 8) {
        float a0[4] = {0.f,0.f,0.f,0.f}, a1[4] = {0.f,0.f,0.f,0.f};
        #pragma unroll 4
        for (int i = 0; i < K_; i++) {
            float wt = tv[i*128 + rr];
            const float* f = fb + ((size_t)ti[i*128 + rr] << 8) + lane*8;
            float4 u  = *(const float4*)f;
            float4 u2 = *(const float4*)(f + 4);
            a0[0]+=wt*u.x;  a0[1]+=wt*u.y;  a0[2]+=wt*u.z;  a0[3]+=wt*u.w;
            a1[0]+=wt*u2.x; a1[1]+=wt*u2.y; a1[2]+=wt*u2.z; a1[3]+=wt*u2.w;
        }
        float* o = out + (((size_t)batch * N_ + q0 + rr) << 8) + lane*8;
        *(float4*)o       = make_float4(a0[0],a0[1],a0[2],a0[3]);
        *(float4*)(o + 4) = make_float4(a1[0],a1[1],a1[2],a1[3]);
    }
}

// ---------------------------------------------------------------------------
extern "C" void kernel_launch(void* const* d_in, const int* in_sizes, int n_in,
                              void* d_out, int out_size)
{
    const float* x    = (const float*)d_in[0];
    const float* W    = (const float*)d_in[1];
    const float* bias = (const float*)d_in[2];
    float* out = (float*)d_out;

    gemm_feat_pos<<<dim3(512/64, M_/64), 256>>>(x, W, bias);
    norm_pos<<<M_, 64>>>();

    const int smem_bytes = SMEM_FLOATS * (int)sizeof(float);
    cudaFuncSetAttribute(topk_attn, cudaFuncAttributeMaxDynamicSharedMemorySize,
                         smem_bytes);
    topk_attn<<<dim3(N_/128, B_), 256, smem_bytes>>>(out);
}

// round 15
// speedup vs baseline: 2.5329x; 1.0539x over previous
#include <cuda_runtime.h>
#include <math.h>
#include <stdint.h>

#define B_ 8
#define N_ 4096
#define C_ 256
#define K_ 32
#define M_ (B_*N_)

// Scratch
__device__ __align__(16) float g_feat[M_*C_];
__device__ __align__(16) float g_pos[M_*C_];

// ---- packed fp32x2 helpers (FFMA2 via PTX fma.rn.f32x2) ----
__device__ __forceinline__ unsigned long long pack2(float x) {
    unsigned long long r;
    asm("mov.b64 %0, {%1, %1};" : "=l"(r) : "f"(x));
    return r;
}
__device__ __forceinline__ void fma2(unsigned long long& d,
                                     unsigned long long a, unsigned long long b) {
    asm("fma.rn.f32x2 %0, %1, %2, %0;" : "+l"(d) : "l"(a), "l"(b));
}
__device__ __forceinline__ float2 unpack2(unsigned long long v) {
    float2 f;
    asm("mov.b64 {%0, %1}, %2;" : "=f"(f.x), "=f"(f.y) : "l"(v));
    return f;
}

// ---------------------------------------------------------------------------
// Kernel 1: feat_pos = x @ W^T + bias ; split into g_feat / g_pos  (R5 proven)
// ---------------------------------------------------------------------------
__global__ __launch_bounds__(256) void gemm_feat_pos(
    const float* __restrict__ x, const float* __restrict__ W,
    const float* __restrict__ bias)
{
    __shared__ float as[16][64];
    __shared__ float bs[16][64];
    const int tid = threadIdx.x;
    const int row0 = blockIdx.y * 64;
    const int d0   = blockIdx.x * 64;
    const int tx = tid & 15, ty = tid >> 4;
    const int lr = tid >> 2, lc = tid & 3;
    float acc[4][4] = {};
    for (int kt = 0; kt < C_; kt += 16) {
        float4 va = *(const float4*)&x[(row0 + lr) * C_ + kt + lc * 4];
        float4 vb = *(const float4*)&W[(d0 + lr) * C_ + kt + lc * 4];
        as[lc*4+0][lr]=va.x; as[lc*4+1][lr]=va.y; as[lc*4+2][lr]=va.z; as[lc*4+3][lr]=va.w;
        bs[lc*4+0][lr]=vb.x; bs[lc*4+1][lr]=vb.y; bs[lc*4+2][lr]=vb.z; bs[lc*4+3][lr]=vb.w;
        __syncthreads();
        #pragma unroll
        for (int kk = 0; kk < 16; kk++) {
            float4 a = *(const float4*)&as[kk][ty*4];
            float4 b = *(const float4*)&bs[kk][tx*4];
            float ar[4]={a.x,a.y,a.z,a.w}, br[4]={b.x,b.y,b.z,b.w};
            #pragma unroll
            for (int i=0;i<4;i++)
                #pragma unroll
                for (int j=0;j<4;j++) acc[i][j] += ar[i]*br[j];
        }
        __syncthreads();
    }
    #pragma unroll
    for (int i=0;i<4;i++) {
        int row = row0 + ty*4 + i;
        #pragma unroll
        for (int j=0;j<4;j++) {
            int d = d0 + tx*4 + j;
            float v = acc[i][j] + bias[d];
            if (d < C_) g_feat[row*C_ + d] = v;
            else        g_pos[row*C_ + d - C_] = v;
        }
    }
}

// ---------------------------------------------------------------------------
// Kernel 2: normalize pos rows in place. grid = M, block = 64  (R5 proven)
// ---------------------------------------------------------------------------
__global__ __launch_bounds__(64) void norm_pos()
{
    const int row = blockIdx.x;
    float* p = g_pos + (size_t)row * C_;
    const int t = threadIdx.x;
    float4 v = *(float4*)&p[t*4];
    float ss = v.x*v.x + v.y*v.y + v.z*v.z + v.w*v.w;
    #pragma unroll
    for (int o = 16; o; o >>= 1) ss += __shfl_xor_sync(0xFFFFFFFFu, ss, o);
    __shared__ float s2[2];
    if ((t & 31) == 0) s2[t >> 5] = ss;
    __syncthreads();
    float inv = 1.0f / fmaxf(sqrtf(s2[0] + s2[1]), 1e-12f);
    v.x*=inv; v.y*=inv; v.z*=inv; v.w*=inv;
    *(float4*)&p[t*4] = v;
}

// ---------------------------------------------------------------------------
// Kernel 3: fused sim GEMM (FFMA2, 8x8 microtile) + top-32 + softmax + gather
// 128 q-rows x 128-key tiles, 256 threads, 8 rows x 8 cols per thread:
//   per kk: 2 LDS.128 A + 2 LDS.128 B (0.75 B/MAC) + 8 pack movs + 32 FFMA2.
// S dumped & scanned in two 64-col phases (S buffer stays 128x65).
// smem float layout:
//   AB  [2][8][128]  q chunk (c-major)   off 0      len 2048
//   BB  [2][8][128]  key chunk           off 2048   len 2048
//   S   [128][65]    S half-tile         off 4096   len 8320
//   TV  [32][128]    top values          off 12416  len 4096
//   TI  u16[32][128] top indices         off 16512  len 2048 (floats)
// total 18560 floats = 74240 B -> 2 blocks/SM, grid 256 = 1 wave
// ---------------------------------------------------------------------------
#define AB0   0
#define BB0   2048
#define SOFF  4096
#define TVOFF 12416
#define TIOFF 16512
#define SMEM_FLOATS 18560

__global__ __launch_bounds__(256, 2) void topk_attn(float* __restrict__ out)
{
    extern __shared__ float sm[];
    float* S  = sm + SOFF;
    float* tv = sm + TVOFF;
    uint16_t* ti = (uint16_t*)(sm + TIOFF);

    const int tid = threadIdx.x;
    const int w = tid >> 5, lane = tid & 31;
    const int batch = blockIdx.y;
    const int q0 = blockIdx.x * 128;
    const float* posb = g_pos + ((size_t)batch * N_ << 8);

    const int tx = tid & 15, ty = tid >> 4;      // 16x16 thread grid
    const int lrow = tid >> 1, seg = tid & 1;    // loader map: 128 rows x 2 segs

    // per-row top-k state (thread tid<128 owns q-row tid)
    int cnt = 0, thrp = 0;
    float thrv = 3.0e38f;

    for (int tile = 0; tile < 32; tile++) {
        const int kt0 = tile * 128;
        // acc2[i2][j]: rows (ty*8+2*i2, +1) x col (tx*8+j), packed f32x2
        unsigned long long acc2[4][8] = {};

        // prefetch chunk 0 (dims seg*4 .. seg*4+3)
        float4 pa = *(const float4*)&posb[((q0 + lrow) << 8) + seg*4];
        float4 pb = *(const float4*)&posb[((kt0 + lrow) << 8) + seg*4];

        for (int ch = 0; ch < 32; ch++) {
            const int buf = ch & 1;
            // store prefetched regs -> smem (c-major)
            {
                float* A = sm + AB0 + buf*1024;
                float* Bp = sm + BB0 + buf*1024;
                A[(seg*4+0)*128 + lrow] = pa.x;
                A[(seg*4+1)*128 + lrow] = pa.y;
                A[(seg*4+2)*128 + lrow] = pa.z;
                A[(seg*4+3)*128 + lrow] = pa.w;
                Bp[(seg*4+0)*128 + lrow] = pb.x;
                Bp[(seg*4+1)*128 + lrow] = pb.y;
                Bp[(seg*4+2)*128 + lrow] = pb.z;
                Bp[(seg*4+3)*128 + lrow] = pb.w;
            }
            // prefetch next chunk
            if (ch + 1 < 32) {
                const int c0 = (ch + 1) * 8 + seg*4;
                pa = *(const float4*)&posb[((q0 + lrow) << 8) + c0];
                pb = *(const float4*)&posb[((kt0 + lrow) << 8) + c0];
            }
            __syncthreads();
            // compute 8 kk on this buffer (double-buffered, no trailing sync)
            const float* A  = sm + AB0 + buf*1024;
            const float* Bp = sm + BB0 + buf*1024;
            #pragma unroll
            for (int kk = 0; kk < 8; kk++) {
                ulonglong2 a01 = *(const ulonglong2*)&A[kk*128 + ty*8];     // rows 0..3
                ulonglong2 a23 = *(const ulonglong2*)&A[kk*128 + ty*8 + 4]; // rows 4..7
                float4 b0 = *(const float4*)&Bp[kk*128 + tx*8];
                float4 b1 = *(const float4*)&Bp[kk*128 + tx*8 + 4];
                unsigned long long ar[4] = {a01.x, a01.y, a23.x, a23.y};
                unsigned long long bp[8] = {pack2(b0.x), pack2(b0.y), pack2(b0.z), pack2(b0.w),
                                            pack2(b1.x), pack2(b1.y), pack2(b1.z), pack2(b1.w)};
                #pragma unroll
                for (int i2 = 0; i2 < 4; i2++)
                    #pragma unroll
                    for (int j = 0; j < 8; j++)
                        fma2(acc2[i2][j], ar[i2], bp[j]);
            }
        }
        __syncthreads();

        // dump + scan in two 64-col phases
        #pragma unroll
        for (int p = 0; p < 2; p++) {
            if ((tx >> 3) == p) {
                const int cb = (tx & 7) * 8;
                #pragma unroll
                for (int i2 = 0; i2 < 4; i2++) {
                    float* r0 = &S[(ty*8 + i2*2)*65 + cb];
                    float* r1 = &S[(ty*8 + i2*2 + 1)*65 + cb];
                    #pragma unroll
                    for (int j = 0; j < 8; j++) {
                        float2 f = unpack2(acc2[i2][j]);
                        r0[j] = f.x;
                        r1[j] = f.y;
                    }
                }
            }
            __syncthreads();
            if (tid < 128) {
                const int r = tid;
                const int kbase = kt0 + p*64;
                #pragma unroll 8
                for (int j = 0; j < 64; j++) {
                    float v = S[r*65 + j];
                    if (cnt < K_) {
                        tv[cnt*128 + r] = v; ti[cnt*128 + r] = (uint16_t)(kbase + j);
                        if (v < thrv) { thrv = v; thrp = cnt; }
                        cnt++;
                    } else if (v > thrv) {
                        tv[thrp*128 + r] = v; ti[thrp*128 + r] = (uint16_t)(kbase + j);
                        thrv = tv[r]; thrp = 0;
                        #pragma unroll
                        for (int i = 1; i < K_; i++) {
                            float t2 = tv[i*128 + r];
                            if (t2 < thrv) { thrv = t2; thrp = i; }
                        }
                    }
                }
            }
            __syncthreads();
        }
    }

    // softmax per row (order-invariant)
    if (tid < 128) {
        const int r = tid;
        float m = -3.0e38f;
        #pragma unroll
        for (int i = 0; i < K_; i++) m = fmaxf(m, tv[i*128 + r]);
        float s = 0.f;
        #pragma unroll
        for (int i = 0; i < K_; i++) { float e = expf(tv[i*128 + r] - m); tv[i*128 + r] = e; s += e; }
        float inv = 1.0f / s;
        #pragma unroll
        for (int i = 0; i < K_; i++) tv[i*128 + r] *= inv;
    }
    __syncthreads();

    // gather: 8 warps, 16 rows each, 8 floats/lane
    const float* fb = g_feat + ((size_t)batch * N_ << 8);
    for (int rr = w; rr < 128; rr += 8) {
        float a0[4] = {0.f,0.f,0.f,0.f}, a1[4] = {0.f,0.f,0.f,0.f};
        #pragma unroll 4
        for (int i = 0; i < K_; i++) {
            float wt = tv[i*128 + rr];
            const float* f = fb + ((size_t)ti[i*128 + rr] << 8) + lane*8;
            float4 u  = *(const float4*)f;
            float4 u2 = *(const float4*)(f + 4);
            a0[0]+=wt*u.x;  a0[1]+=wt*u.y;  a0[2]+=wt*u.z;  a0[3]+=wt*u.w;
            a1[0]+=wt*u2.x; a1[1]+=wt*u2.y; a1[2]+=wt*u2.z; a1[3]+=wt*u2.w;
        }
        float* o = out + (((size_t)batch * N_ + q0 + rr) << 8) + lane*8;
        *(float4*)o       = make_float4(a0[0],a0[1],a0[2],a0[3]);
        *(float4*)(o + 4) = make_float4(a1[0],a1[1],a1[2],a1[3]);
    }
}

// ---------------------------------------------------------------------------
extern "C" void kernel_launch(void* const* d_in, const int* in_sizes, int n_in,
                              void* d_out, int out_size)
{
    const float* x    = (const float*)d_in[0];
    const float* W    = (const float*)d_in[1];
    const float* bias = (const float*)d_in[2];
    float* out = (float*)d_out;

    gemm_feat_pos<<<dim3(512/64, M_/64), 256>>>(x, W, bias);
    norm_pos<<<M_, 64>>>();

    const int smem_bytes = SMEM_FLOATS * (int)sizeof(float);
    cudaFuncSetAttribute(topk_attn, cudaFuncAttributeMaxDynamicSharedMemorySize,
                         smem_bytes);
    topk_attn<<<dim3(N_/128, B_), 256, smem_bytes>>>(out);
}